// round 9
// baseline (speedup 1.0000x reference)
#include <cuda_runtime.h>

// RAE GRU enc-dec. K0: pad+transpose Wih. K1: precompute all encoder gi.
// K2: encoder recurrence (ping-pong h, 1 named team-barrier/step).
// K3: decoder recurrence (lin_W folded into GEMM, 2 team-barriers/step).
// The 4 rowgroups (4 warps each) of a CTA are fully independent: they share
// only read-only weights, so bar.sync(team,128) replaces __syncthreads.

typedef unsigned long long u64;

__device__ __forceinline__ u64 pk2(float lo, float hi) {
    u64 r; asm("mov.b64 %0, {%1,%2};" : "=l"(r) : "f"(lo), "f"(hi)); return r;
}
__device__ __forceinline__ float red2(u64 v) {
    float lo, hi; asm("mov.b64 {%0,%1}, %2;" : "=f"(lo), "=f"(hi) : "l"(v));
    return lo + hi;
}
__device__ __forceinline__ void fma2(u64& d, u64 a, u64 b) {
    asm("fma.rn.f32x2 %0, %1, %2, %0;" : "+l"(d) : "l"(a), "l"(b));
}
// fast sigmoid / tanh: MUFU EX2 + RCP, ~1e-6 accurate, correct saturation
__device__ __forceinline__ float sigm(float v) {
    return __fdividef(1.f, 1.f + __expf(-v));
}
__device__ __forceinline__ float tanh_fast(float v) {
    return 1.f - 2.f * __fdividef(1.f, __expf(2.f * v) + 1.f);
}
__device__ __forceinline__ void team_bar(int id) {
    asm volatile("bar.sync %0, 128;" :: "r"(id) : "memory");
}

constexpr int X  = 38;
constexpr int XP = 40;
constexpr int H  = 128;
constexpr int G  = 384;
constexpr int GO = G + X;   // 422: gates + folded lin_W cols
constexpr int T  = 128;
constexpr int B  = 2048;
constexpr int BT = 16;
constexpr int NB = B / BT;  // 128 CTAs

// transposed padded Wih staging: [kb][col][kk]  (coalesced 16B per col)
__device__ float g_wih_t[(XP / 4) * G * 4];
__device__ float g_dwih_t[(XP / 4) * G * 4];
__device__ float g_henc[B * H];
__device__ float g_gi[B * T * G];

// ----------------------------- K0: pad/transpose Wih -----------------------
__global__ void pad_wih_kernel(const float* __restrict__ ewih,
                               const float* __restrict__ dwih) {
    int i = blockIdx.x * blockDim.x + threadIdx.x;
    if (i < G * XP) {
        int col = i / XP, k = i - col * XP;
        int dst = (k >> 2) * (G * 4) + col * 4 + (k & 3);
        g_wih_t[dst]  = (k < X) ? ewih[col * X + k] : 0.f;
        g_dwih_t[dst] = (k < X) ? dwih[col * X + k] : 0.f;
    }
}

// ------------------- K1: encoder gi precompute GEMM ------------------------
constexpr int K1R = 32;
__global__ void __launch_bounds__(512, 1)
gi_kernel(const float* __restrict__ x, const float* __restrict__ ebih) {
    __shared__ float xs[K1R * XP];
    const int tid = threadIdx.x;
    const int gr0 = blockIdx.x * K1R;

    for (int i = tid; i < K1R * XP; i += 512) {
        int rr = i / XP, k = i - rr * XP;
        xs[i] = (k < X) ? x[(gr0 + rr) * X + k] : 0.f;
    }
    __syncthreads();

    const int rg = tid >> 7;
    const int ct = tid & 127;
    const int r0 = rg << 3;

    u64 acc[8][3];
    #pragma unroll
    for (int i = 0; i < 3; ++i) {
        float bi = ebih[ct + (i << 7)];
        #pragma unroll
        for (int r = 0; r < 8; ++r) acc[r][i] = pk2(bi, 0.f);
    }
    #pragma unroll
    for (int kb = 0; kb < XP / 4; ++kb) {
        int k = kb << 2;
        ulonglong2 xv[8];
        #pragma unroll
        for (int r = 0; r < 8; ++r)
            xv[r] = *(const ulonglong2*)(xs + (r0 + r) * XP + k);
        #pragma unroll
        for (int i = 0; i < 3; ++i) {
            ulonglong2 wv = *(const ulonglong2*)(g_wih_t + kb * (G * 4) + (ct + (i << 7)) * 4);
            #pragma unroll
            for (int r = 0; r < 8; ++r) {
                fma2(acc[r][i], xv[r].x, wv.x);
                fma2(acc[r][i], xv[r].y, wv.y);
            }
        }
    }
    #pragma unroll
    for (int r = 0; r < 8; ++r) {
        int gr = gr0 + r0 + r;
        int b = gr >> 7, t = gr & (T - 1);
        int blk = b >> 4, lb = b & 15;
        int base = ((blk * T + t) * BT + lb) * G;
        #pragma unroll
        for (int i = 0; i < 3; ++i) g_gi[base + ct + (i << 7)] = red2(acc[r][i]);
    }
}

// ------------------------- K2: encoder recurrence --------------------------
constexpr int ENC_SMB = (G * H + 2 * BT * H) * 4;   // 212992 B

__global__ void __launch_bounds__(512, 1)
enc_kernel(const float* __restrict__ eWhh, const float* __restrict__ ebhh) {
    extern __shared__ float sm[];
    float* Ws = sm;
    float* hA = Ws + G * H;
    float* hB = hA + BT * H;

    const int tid = threadIdx.x;
    const int rg  = tid >> 7;
    const int ct  = tid & 127;
    const int r0  = rg << 2;
    const int swz = (ct & 31) << 2;
    const int blk = blockIdx.x;
    const int bid = rg + 1;   // named barrier id for this team

    for (int i = tid; i < G * H; i += 512) {
        int c = i >> 7, k = i & 127;
        Ws[(c << 7) + (k ^ ((c & 31) << 2))] = eWhh[i];
    }
    for (int i = tid; i < BT * H; i += 512) hA[i] = 0.f;
    float bh[3];
    #pragma unroll
    for (int i = 0; i < 3; ++i) bh[i] = ebhh[ct + (i << 7)];
    __syncthreads();

    float* hR = hA;
    float* hW = hB;

    for (int t = 0; t < T; ++t) {
        // dependency-free gi prefetch (covered by the gh GEMM)
        float gv[4][3];
        int gbase = (blk * T + t) * BT * G;
        #pragma unroll
        for (int r = 0; r < 4; ++r)
            #pragma unroll
            for (int i = 0; i < 3; ++i)
                gv[r][i] = __ldg(&g_gi[gbase + (r0 + r) * G + ct + (i << 7)]);

        u64 aH[4][3];
        #pragma unroll
        for (int r = 0; r < 4; ++r)
            #pragma unroll
            for (int i = 0; i < 3; ++i) aH[r][i] = pk2(bh[i], 0.f);

        #pragma unroll 8
        for (int kb = 0; kb < H / 4; ++kb) {
            int k = kb << 2;
            ulonglong2 hv[4];
            #pragma unroll
            for (int r = 0; r < 4; ++r)
                hv[r] = *(const ulonglong2*)(hR + (r0 + r) * H + k);
            #pragma unroll
            for (int i = 0; i < 3; ++i) {
                ulonglong2 wv = *(const ulonglong2*)(Ws + ((ct + (i << 7)) << 7) + (k ^ swz));
                #pragma unroll
                for (int r = 0; r < 4; ++r) {
                    fma2(aH[r][i], hv[r].x, wv.x);
                    fma2(aH[r][i], hv[r].y, wv.y);
                }
            }
        }

        // write into the inactive buffer: no hazard -> 1 team-barrier/step
        #pragma unroll
        for (int r = 0; r < 4; ++r) {
            float rr = sigm(gv[r][0] + red2(aH[r][0]));
            float zz = sigm(gv[r][1] + red2(aH[r][1]));
            float nn = tanh_fast(gv[r][2] + rr * red2(aH[r][2]));
            float ho = hR[(r0 + r) * H + ct];
            hW[(r0 + r) * H + ct] = (1.f - zz) * nn + zz * ho;
        }
        team_bar(bid);
        float* tmp = hR; hR = hW; hW = tmp;
    }
    __syncthreads();
    for (int i = tid; i < BT * H; i += 512) g_henc[blk * BT * H + i] = hR[i];
}

// ------------------------- K3: decoder recurrence --------------------------
constexpr int DEC_SMB = (GO * H + BT * H + BT * XP) * 4;  // 226816 B

__global__ void __launch_bounds__(512, 1)
dec_kernel(const float* __restrict__ dWhh,
           const float* __restrict__ dbih, const float* __restrict__ dbhh,
           const float* __restrict__ linW, const float* __restrict__ linb,
           float* __restrict__ out) {
    extern __shared__ float sm[];
    float* Ws = sm;
    float* hS = Ws + GO * H;
    float* oS = hS + BT * H;

    const int tid = threadIdx.x;
    const int rg  = tid >> 7;
    const int ct  = tid & 127;
    const int r0  = rg << 2;
    const int swz = (ct & 31) << 2;
    const int blk = blockIdx.x;
    const int bid = rg + 1;
    const bool oc = (ct < X);

    for (int i = tid; i < GO * H; i += 512) {
        int c = i >> 7, k = i & 127;
        float v = (c < G) ? dWhh[i] : linW[(c - G) * H + k];
        Ws[(c << 7) + (k ^ ((c & 31) << 2))] = v;
    }
    for (int i = tid; i < BT * H; i += 512) hS[i] = g_henc[blk * BT * H + i];
    for (int i = tid; i < BT * XP; i += 512) oS[i] = 0.f;   // GO = 0
    float bh[3], bi[3];
    #pragma unroll
    for (int i = 0; i < 3; ++i) { bh[i] = dbhh[ct + (i << 7)]; bi[i] = dbih[ct + (i << 7)]; }
    const float lb = oc ? linb[ct] : 0.f;
    __syncthreads();

    // iter t: GEMM(h_{t-1}) -> gh gates + o_{t-1}=lin(h_{t-1})=out[t-1];
    // gi from o_{t-1}; update h. iter t==T only emits out[T-1].
    for (int t = 0; t <= T; ++t) {
        u64 aH[4][3];
        u64 aL[4];
        #pragma unroll
        for (int r = 0; r < 4; ++r) {
            #pragma unroll
            for (int i = 0; i < 3; ++i) aH[r][i] = pk2(bh[i], 0.f);
            aL[r] = pk2(lb, 0.f);
        }
        #pragma unroll 8
        for (int kb = 0; kb < H / 4; ++kb) {
            int k = kb << 2;
            ulonglong2 hv[4];
            #pragma unroll
            for (int r = 0; r < 4; ++r)
                hv[r] = *(const ulonglong2*)(hS + (r0 + r) * H + k);
            #pragma unroll
            for (int i = 0; i < 3; ++i) {
                ulonglong2 wv = *(const ulonglong2*)(Ws + ((ct + (i << 7)) << 7) + (k ^ swz));
                #pragma unroll
                for (int r = 0; r < 4; ++r) {
                    fma2(aH[r][i], hv[r].x, wv.x);
                    fma2(aH[r][i], hv[r].y, wv.y);
                }
            }
            if (oc) {
                ulonglong2 wl = *(const ulonglong2*)(Ws + ((G + ct) << 7) + (k ^ swz));
                #pragma unroll
                for (int r = 0; r < 4; ++r) {
                    fma2(aL[r], hv[r].x, wl.x);
                    fma2(aL[r], hv[r].y, wl.y);
                }
            }
        }
        float gh0[4], gh1[4], gh2[4];
        #pragma unroll
        for (int r = 0; r < 4; ++r) {
            gh0[r] = red2(aH[r][0]); gh1[r] = red2(aH[r][1]); gh2[r] = red2(aH[r][2]);
        }
        if (oc && t > 0) {
            #pragma unroll
            for (int r = 0; r < 4; ++r) {
                float ov = red2(aL[r]);
                oS[(r0 + r) * XP + ct] = ov;
                out[((blk * BT + r0 + r) * T + (t - 1)) * X + ct] = ov;
            }
        }
        if (t == T) break;
        team_bar(bid);   // oS published, hS reads complete (team-local)

        // gi = o_prev @ dWih^T + dbih  (coalesced transposed weights, hot L2)
        u64 aI[4][3];
        #pragma unroll
        for (int r = 0; r < 4; ++r)
            #pragma unroll
            for (int i = 0; i < 3; ++i) aI[r][i] = pk2(bi[i], 0.f);
        #pragma unroll
        for (int kb = 0; kb < XP / 4; ++kb) {
            int k = kb << 2;
            ulonglong2 xv[4];
            #pragma unroll
            for (int r = 0; r < 4; ++r)
                xv[r] = *(const ulonglong2*)(oS + (r0 + r) * XP + k);
            #pragma unroll
            for (int i = 0; i < 3; ++i) {
                ulonglong2 wv = *(const ulonglong2*)(g_dwih_t + kb * (G * 4) + (ct + (i << 7)) * 4);
                #pragma unroll
                for (int r = 0; r < 4; ++r) {
                    fma2(aI[r][i], xv[r].x, wv.x);
                    fma2(aI[r][i], xv[r].y, wv.y);
                }
            }
        }

        #pragma unroll
        for (int r = 0; r < 4; ++r) {
            float rr = sigm(red2(aI[r][0]) + gh0[r]);
            float zz = sigm(red2(aI[r][1]) + gh1[r]);
            float nn = tanh_fast(red2(aI[r][2]) + rr * gh2[r]);
            float ho = hS[(r0 + r) * H + ct];
            hS[(r0 + r) * H + ct] = (1.f - zz) * nn + zz * ho;
        }
        team_bar(bid);   // h updated (team-local)
    }
}

extern "C" void kernel_launch(void* const* d_in, const int* in_sizes, int n_in,
                              void* d_out, int out_size) {
    const float* x    = (const float*)d_in[0];
    const float* eWih = (const float*)d_in[1];
    const float* eWhh = (const float*)d_in[2];
    const float* ebih = (const float*)d_in[3];
    const float* ebhh = (const float*)d_in[4];
    const float* dWih = (const float*)d_in[5];
    const float* dWhh = (const float*)d_in[6];
    const float* dbih = (const float*)d_in[7];
    const float* dbhh = (const float*)d_in[8];
    const float* linW = (const float*)d_in[9];
    const float* linb = (const float*)d_in[10];
    float* out = (float*)d_out;

    pad_wih_kernel<<<(G * XP + 255) / 256, 256>>>(eWih, dWih);
    gi_kernel<<<(B * T) / K1R, 512>>>(x, ebih);

    cudaFuncSetAttribute(enc_kernel, cudaFuncAttributeMaxDynamicSharedMemorySize, ENC_SMB);
    enc_kernel<<<NB, 512, ENC_SMB>>>(eWhh, ebhh);

    cudaFuncSetAttribute(dec_kernel, cudaFuncAttributeMaxDynamicSharedMemorySize, DEC_SMB);
    dec_kernel<<<NB, 512, DEC_SMB>>>(dWhh, dbih, dbhh, linW, linb, out);
}

// round 11
// speedup vs baseline: 1.6771x; 1.6771x over previous
#include <cuda_runtime.h>

// RAE GRU enc-dec. K0: pad+transpose Wih. K1: precompute all encoder gi.
// K2/K3: recurrences with 256 threads/CTA, 8 batch rows per thread, 2 teams.
//  - halves smem weight traffic vs 4-team layout (each col read 2x not 4x)
//  - 256 regs/thread lets ptxas pipeline LDS->FFMA2 chains (was 128-capped)
//  - named team barriers (bar.sync id,128), MUFU fast gates

typedef unsigned long long u64;

__device__ __forceinline__ u64 pk2(float lo, float hi) {
    u64 r; asm("mov.b64 %0, {%1,%2};" : "=l"(r) : "f"(lo), "f"(hi)); return r;
}
__device__ __forceinline__ float red2(u64 v) {
    float lo, hi; asm("mov.b64 {%0,%1}, %2;" : "=f"(lo), "=f"(hi) : "l"(v));
    return lo + hi;
}
__device__ __forceinline__ void fma2(u64& d, u64 a, u64 b) {
    asm("fma.rn.f32x2 %0, %1, %2, %0;" : "+l"(d) : "l"(a), "l"(b));
}
__device__ __forceinline__ float sigm(float v) {
    return __fdividef(1.f, 1.f + __expf(-v));
}
__device__ __forceinline__ float tanh_fast(float v) {
    return 1.f - 2.f * __fdividef(1.f, __expf(2.f * v) + 1.f);
}
__device__ __forceinline__ void team_bar(int id) {
    asm volatile("bar.sync %0, 128;" :: "r"(id) : "memory");
}

constexpr int X  = 38;
constexpr int XP = 40;
constexpr int H  = 128;
constexpr int G  = 384;
constexpr int GO = G + X;   // 422
constexpr int T  = 128;
constexpr int B  = 2048;
constexpr int BT = 16;
constexpr int NB = B / BT;  // 128 CTAs
constexpr int NT = 256;     // threads per recurrent CTA
constexpr int RR = 8;       // batch rows per thread

__device__ float g_wih_t[(XP / 4) * G * 4];
__device__ float g_dwih_t[(XP / 4) * G * 4];
__device__ float g_henc[B * H];
__device__ float g_gi[B * T * G];

// ----------------------------- K0: pad/transpose Wih -----------------------
__global__ void pad_wih_kernel(const float* __restrict__ ewih,
                               const float* __restrict__ dwih) {
    int i = blockIdx.x * blockDim.x + threadIdx.x;
    if (i < G * XP) {
        int col = i / XP, k = i - col * XP;
        int dst = (k >> 2) * (G * 4) + col * 4 + (k & 3);
        g_wih_t[dst]  = (k < X) ? ewih[col * X + k] : 0.f;
        g_dwih_t[dst] = (k < X) ? dwih[col * X + k] : 0.f;
    }
}

// ------------------- K1: encoder gi precompute GEMM ------------------------
constexpr int K1R = 32;
__global__ void __launch_bounds__(512, 1)
gi_kernel(const float* __restrict__ x, const float* __restrict__ ebih) {
    __shared__ float xs[K1R * XP];
    const int tid = threadIdx.x;
    const int gr0 = blockIdx.x * K1R;

    for (int i = tid; i < K1R * XP; i += 512) {
        int rr = i / XP, k = i - rr * XP;
        xs[i] = (k < X) ? x[(gr0 + rr) * X + k] : 0.f;
    }
    __syncthreads();

    const int rg = tid >> 7;
    const int ct = tid & 127;
    const int r0 = rg << 3;

    u64 acc[8][3];
    #pragma unroll
    for (int i = 0; i < 3; ++i) {
        float bi = ebih[ct + (i << 7)];
        #pragma unroll
        for (int r = 0; r < 8; ++r) acc[r][i] = pk2(bi, 0.f);
    }
    #pragma unroll
    for (int kb = 0; kb < XP / 4; ++kb) {
        int k = kb << 2;
        ulonglong2 xv[8];
        #pragma unroll
        for (int r = 0; r < 8; ++r)
            xv[r] = *(const ulonglong2*)(xs + (r0 + r) * XP + k);
        #pragma unroll
        for (int i = 0; i < 3; ++i) {
            ulonglong2 wv = *(const ulonglong2*)(g_wih_t + kb * (G * 4) + (ct + (i << 7)) * 4);
            #pragma unroll
            for (int r = 0; r < 8; ++r) {
                fma2(acc[r][i], xv[r].x, wv.x);
                fma2(acc[r][i], xv[r].y, wv.y);
            }
        }
    }
    #pragma unroll
    for (int r = 0; r < 8; ++r) {
        int gr = gr0 + r0 + r;
        int b = gr >> 7, t = gr & (T - 1);
        int blk = b >> 4, lb = b & 15;
        int base = ((blk * T + t) * BT + lb) * G;
        #pragma unroll
        for (int i = 0; i < 3; ++i) g_gi[base + ct + (i << 7)] = red2(acc[r][i]);
    }
}

// ------------------------- K2: encoder recurrence --------------------------
constexpr int ENC_SMB = (G * H + 2 * BT * H) * 4;   // 212992 B

__global__ void __launch_bounds__(NT, 1)
enc_kernel(const float* __restrict__ eWhh, const float* __restrict__ ebhh) {
    extern __shared__ float sm[];
    float* Ws = sm;
    float* hA = Ws + G * H;
    float* hB = hA + BT * H;

    const int tid = threadIdx.x;
    const int tm  = tid >> 7;         // team 0/1
    const int ct  = tid & 127;
    const int r0  = tm << 3;          // 8 rows per team
    const int swz = (ct & 31) << 2;
    const int blk = blockIdx.x;
    const int bid = tm + 1;

    for (int i = tid; i < G * H; i += NT) {
        int c = i >> 7, k = i & 127;
        Ws[(c << 7) + (k ^ ((c & 31) << 2))] = eWhh[i];
    }
    for (int i = tid; i < BT * H; i += NT) hA[i] = 0.f;
    float bh[3];
    #pragma unroll
    for (int i = 0; i < 3; ++i) bh[i] = ebhh[ct + (i << 7)];
    __syncthreads();

    float* hR = hA;
    float* hW = hB;

    for (int t = 0; t < T; ++t) {
        // dependency-free gi prefetch (covered by the gh GEMM)
        float gv[RR][3];
        int gbase = (blk * T + t) * BT * G;
        #pragma unroll
        for (int r = 0; r < RR; ++r)
            #pragma unroll
            for (int i = 0; i < 3; ++i)
                gv[r][i] = __ldg(&g_gi[gbase + (r0 + r) * G + ct + (i << 7)]);

        u64 aH[RR][3];
        #pragma unroll
        for (int r = 0; r < RR; ++r)
            #pragma unroll
            for (int i = 0; i < 3; ++i) aH[r][i] = pk2(bh[i], 0.f);

        #pragma unroll 4
        for (int kb = 0; kb < H / 4; ++kb) {
            int k = kb << 2;
            ulonglong2 hv[RR];
            #pragma unroll
            for (int r = 0; r < RR; ++r)
                hv[r] = *(const ulonglong2*)(hR + (r0 + r) * H + k);
            #pragma unroll
            for (int i = 0; i < 3; ++i) {
                ulonglong2 wv = *(const ulonglong2*)(Ws + ((ct + (i << 7)) << 7) + (k ^ swz));
                #pragma unroll
                for (int r = 0; r < RR; ++r) {
                    fma2(aH[r][i], hv[r].x, wv.x);
                    fma2(aH[r][i], hv[r].y, wv.y);
                }
            }
        }

        #pragma unroll
        for (int r = 0; r < RR; ++r) {
            float rr = sigm(gv[r][0] + red2(aH[r][0]));
            float zz = sigm(gv[r][1] + red2(aH[r][1]));
            float nn = tanh_fast(gv[r][2] + rr * red2(aH[r][2]));
            float ho = hR[(r0 + r) * H + ct];
            hW[(r0 + r) * H + ct] = (1.f - zz) * nn + zz * ho;
        }
        team_bar(bid);
        float* tmp = hR; hR = hW; hW = tmp;
    }
    __syncthreads();
    for (int i = tid; i < BT * H; i += NT) g_henc[blk * BT * H + i] = hR[i];
}

// ------------------------- K3: decoder recurrence --------------------------
constexpr int DEC_SMB = (GO * H + BT * H + BT * XP) * 4;  // 226816 B

__global__ void __launch_bounds__(NT, 1)
dec_kernel(const float* __restrict__ dWhh,
           const float* __restrict__ dbih, const float* __restrict__ dbhh,
           const float* __restrict__ linW, const float* __restrict__ linb,
           float* __restrict__ out) {
    extern __shared__ float sm[];
    float* Ws = sm;
    float* hS = Ws + GO * H;
    float* oS = hS + BT * H;

    const int tid = threadIdx.x;
    const int tm  = tid >> 7;
    const int ct  = tid & 127;
    const int r0  = tm << 3;
    const int swz = (ct & 31) << 2;
    const int blk = blockIdx.x;
    const int bid = tm + 1;
    const bool oc = (ct < X);

    for (int i = tid; i < GO * H; i += NT) {
        int c = i >> 7, k = i & 127;
        float v = (c < G) ? dWhh[i] : linW[(c - G) * H + k];
        Ws[(c << 7) + (k ^ ((c & 31) << 2))] = v;
    }
    for (int i = tid; i < BT * H; i += NT) hS[i] = g_henc[blk * BT * H + i];
    for (int i = tid; i < BT * XP; i += NT) oS[i] = 0.f;   // GO = 0
    float bh[3], bi[3];
    #pragma unroll
    for (int i = 0; i < 3; ++i) { bh[i] = dbhh[ct + (i << 7)]; bi[i] = dbih[ct + (i << 7)]; }
    const float lb = oc ? linb[ct] : 0.f;
    __syncthreads();

    // iter t: GEMM(h_{t-1}) -> gh gates + o_{t-1}=lin(h_{t-1})=out[t-1];
    // gi from o_{t-1}; update h. iter t==T only emits out[T-1].
    for (int t = 0; t <= T; ++t) {
        u64 aH[RR][3];
        u64 aL[RR];
        #pragma unroll
        for (int r = 0; r < RR; ++r) {
            #pragma unroll
            for (int i = 0; i < 3; ++i) aH[r][i] = pk2(bh[i], 0.f);
            aL[r] = pk2(lb, 0.f);
        }
        #pragma unroll 4
        for (int kb = 0; kb < H / 4; ++kb) {
            int k = kb << 2;
            ulonglong2 hv[RR];
            #pragma unroll
            for (int r = 0; r < RR; ++r)
                hv[r] = *(const ulonglong2*)(hS + (r0 + r) * H + k);
            #pragma unroll
            for (int i = 0; i < 3; ++i) {
                ulonglong2 wv = *(const ulonglong2*)(Ws + ((ct + (i << 7)) << 7) + (k ^ swz));
                #pragma unroll
                for (int r = 0; r < RR; ++r) {
                    fma2(aH[r][i], hv[r].x, wv.x);
                    fma2(aH[r][i], hv[r].y, wv.y);
                }
            }
            if (oc) {
                ulonglong2 wl = *(const ulonglong2*)(Ws + ((G + ct) << 7) + (k ^ swz));
                #pragma unroll
                for (int r = 0; r < RR; ++r) {
                    fma2(aL[r], hv[r].x, wl.x);
                    fma2(aL[r], hv[r].y, wl.y);
                }
            }
        }
        float gh0[RR], gh1[RR], gh2[RR];
        #pragma unroll
        for (int r = 0; r < RR; ++r) {
            gh0[r] = red2(aH[r][0]); gh1[r] = red2(aH[r][1]); gh2[r] = red2(aH[r][2]);
        }
        if (oc && t > 0) {
            #pragma unroll
            for (int r = 0; r < RR; ++r) {
                float ov = red2(aL[r]);
                oS[(r0 + r) * XP + ct] = ov;
                out[((blk * BT + r0 + r) * T + (t - 1)) * X + ct] = ov;
            }
        }
        if (t == T) break;
        team_bar(bid);   // oS published, hS reads complete (team-local)

        // gi = o_prev @ dWih^T + dbih  (coalesced transposed weights, hot L2)
        u64 aI[RR][3];
        #pragma unroll
        for (int r = 0; r < RR; ++r)
            #pragma unroll
            for (int i = 0; i < 3; ++i) aI[r][i] = pk2(bi[i], 0.f);
        #pragma unroll
        for (int kb = 0; kb < XP / 4; ++kb) {
            int k = kb << 2;
            ulonglong2 xv[RR];
            #pragma unroll
            for (int r = 0; r < RR; ++r)
                xv[r] = *(const ulonglong2*)(oS + (r0 + r) * XP + k);
            #pragma unroll
            for (int i = 0; i < 3; ++i) {
                ulonglong2 wv = *(const ulonglong2*)(g_dwih_t + kb * (G * 4) + (ct + (i << 7)) * 4);
                #pragma unroll
                for (int r = 0; r < RR; ++r) {
                    fma2(aI[r][i], xv[r].x, wv.x);
                    fma2(aI[r][i], xv[r].y, wv.y);
                }
            }
        }

        #pragma unroll
        for (int r = 0; r < RR; ++r) {
            float rr = sigm(red2(aI[r][0]) + gh0[r]);
            float zz = sigm(red2(aI[r][1]) + gh1[r]);
            float nn = tanh_fast(red2(aI[r][2]) + rr * gh2[r]);
            float ho = hS[(r0 + r) * H + ct];
            hS[(r0 + r) * H + ct] = (1.f - zz) * nn + zz * ho;
        }
        team_bar(bid);   // h updated (team-local)
    }
}

extern "C" void kernel_launch(void* const* d_in, const int* in_sizes, int n_in,
                              void* d_out, int out_size) {
    const float* x    = (const float*)d_in[0];
    const float* eWih = (const float*)d_in[1];
    const float* eWhh = (const float*)d_in[2];
    const float* ebih = (const float*)d_in[3];
    const float* ebhh = (const float*)d_in[4];
    const float* dWih = (const float*)d_in[5];
    const float* dWhh = (const float*)d_in[6];
    const float* dbih = (const float*)d_in[7];
    const float* dbhh = (const float*)d_in[8];
    const float* linW = (const float*)d_in[9];
    const float* linb = (const float*)d_in[10];
    float* out = (float*)d_out;

    pad_wih_kernel<<<(G * XP + 255) / 256, 256>>>(eWih, dWih);
    gi_kernel<<<(B * T) / K1R, 512>>>(x, ebih);

    cudaFuncSetAttribute(enc_kernel, cudaFuncAttributeMaxDynamicSharedMemorySize, ENC_SMB);
    enc_kernel<<<NB, NT, ENC_SMB>>>(eWhh, ebhh);

    cudaFuncSetAttribute(dec_kernel, cudaFuncAttributeMaxDynamicSharedMemorySize, DEC_SMB);
    dec_kernel<<<NB, NT, DEC_SMB>>>(dWhh, dbih, dbhh, linW, linb, out);
}